// round 1
// baseline (speedup 1.0000x reference)
#include <cuda_runtime.h>

#define T_LEN   2048
#define BATCH   16
#define NFREQ   1152
#define NOCT    9
#define NF0     128

// -------- device scratch (no allocations allowed) --------
__device__ float g_yn[BATCH * T_LEN];
__device__ float g_p1[BATCH * NFREQ];
__device__ float g_p2[BATCH * NFREQ];

// -------- helpers --------
__device__ __forceinline__ float warp_sum(float v) {
#pragma unroll
    for (int o = 16; o; o >>= 1) v += __shfl_down_sync(0xffffffffu, v, o);
    return v;
}

// Accurate-enough sincos: round-to-nearest multiple of pi, 3-term Cody-Waite
// reduction, degree-11/12 Taylor polynomials on [-pi/2, pi/2], parity sign flip.
// Valid for |x| up to ~1e5; here |x| <= ~1.5e3. Abs error ~3e-7.
__device__ __forceinline__ void fast_sincos(float x, float& s, float& c) {
    const float INV_PI = 0.3183098861837907f;
    const float PI_A = 3.140625f;
    const float PI_B = 9.67502593994140625e-4f;
    const float PI_C = 1.509957990978376e-7f;

    int   qi = __float2int_rn(x * INV_PI);
    float qf = (float)qi;
    float r  = fmaf(qf, -PI_A, x);
    r = fmaf(qf, -PI_B, r);
    r = fmaf(qf, -PI_C, r);

    float z = r * r;

    // sin poly (deg 11, odd)
    float ps = -2.5052108385441720e-8f;
    ps = fmaf(ps, z,  2.7557319223985893e-6f);
    ps = fmaf(ps, z, -1.9841269841269841e-4f);
    ps = fmaf(ps, z,  8.3333333333333333e-3f);
    ps = fmaf(ps, z, -1.6666666666666666e-1f);
    float sr = fmaf(ps * z, r, r);

    // cos poly (deg 12, even)
    float pc =  2.0876756987868099e-9f;
    pc = fmaf(pc, z, -2.7557319223985893e-7f);
    pc = fmaf(pc, z,  2.4801587301587302e-5f);
    pc = fmaf(pc, z, -1.3888888888888889e-3f);
    pc = fmaf(pc, z,  4.1666666666666666e-2f);
    pc = fmaf(pc, z, -0.5f);
    float cr = fmaf(pc, z, 1.0f);

    unsigned sgn = ((unsigned)qi & 1u) << 31;
    s = __uint_as_float(__float_as_uint(sr) ^ sgn);
    c = __uint_as_float(__float_as_uint(cr) ^ sgn);
}

// -------- kernel 1: per-batch tnorm of ys --------
__global__ __launch_bounds__(256) void normalize_kernel(const float* __restrict__ batch) {
    const int b = blockIdx.x;
    const float* __restrict__ ys = batch + b * (2 * T_LEN) + T_LEN;

    __shared__ float sm[T_LEN];
    __shared__ float rb[8];
    __shared__ float mean_s, inv_s;

    float acc = 0.0f;
    for (int t = threadIdx.x; t < T_LEN; t += 256) {
        float v = ys[t];
        sm[t] = v;
        acc += v;
    }
    acc = warp_sum(acc);
    int lane = threadIdx.x & 31, w = threadIdx.x >> 5;
    if (lane == 0) rb[w] = acc;
    __syncthreads();
    if (w == 0) {
        float v = (lane < 8) ? rb[lane] : 0.0f;
        v = warp_sum(v);
        if (lane == 0) mean_s = v * (1.0f / T_LEN);
    }
    __syncthreads();
    const float mean = mean_s;

    float acc2 = 0.0f;
    for (int t = threadIdx.x; t < T_LEN; t += 256) {
        float d = sm[t] - mean;
        acc2 = fmaf(d, d, acc2);
    }
    acc2 = warp_sum(acc2);
    __syncthreads();              // protect rb reuse
    if (lane == 0) rb[w] = acc2;
    __syncthreads();
    if (w == 0) {
        float v = (lane < 8) ? rb[lane] : 0.0f;
        v = warp_sum(v);
        if (lane == 0) {
            float sd = sqrtf(v * (1.0f / (T_LEN - 1)));
            inv_s = 1.0f / (sd + 1e-4f);
        }
    }
    __syncthreads();
    const float inv = inv_s;
    for (int t = threadIdx.x; t < T_LEN; t += 256)
        g_yn[b * T_LEN + t] = (sm[t] - mean) * inv;
}

// -------- kernel 2: spectral projection (dominant cost) --------
// block = (f0 in [0,128), b in [0,16)); 64 threads, each does 32 time steps.
// Octaves 0..4 built from fresh sincos at freqs[f0] via angle doubling;
// octaves 5..8 from fresh sincos at freqs[f0+640].
__global__ __launch_bounds__(64) void spectral_kernel(const float* __restrict__ batch,
                                                      const float* __restrict__ freqs) {
    const int f0 = blockIdx.x;
    const int b  = blockIdx.y;
    const float* __restrict__ ts = batch + b * (2 * T_LEN);
    const float* __restrict__ yn = g_yn + b * T_LEN;

    const float TWO_PI = 6.283185307179586f;
    const float w0 = freqs[f0]        * TWO_PI;
    const float w1 = freqs[f0 + 640]  * TWO_PI;

    float a1[NOCT], a2[NOCT];
#pragma unroll
    for (int k = 0; k < NOCT; k++) { a1[k] = 0.0f; a2[k] = 0.0f; }

#pragma unroll 2
    for (int t = threadIdx.x; t < T_LEN; t += 64) {
        const float tv = ts[t];
        const float y  = yn[t];
        float s, c;

        fast_sincos(tv * w0, s, c);
#pragma unroll
        for (int k = 0; k < 5; k++) {
            a1[k] = fmaf(y, s, a1[k]);
            a2[k] = fmaf(y, c, a2[k]);
            if (k < 4) {
                float u = s * s;
                float p = s * c;
                c = fmaf(-2.0f, u, 1.0f);
                s = p + p;
            }
        }

        fast_sincos(tv * w1, s, c);
#pragma unroll
        for (int k = 5; k < 9; k++) {
            a1[k] = fmaf(y, s, a1[k]);
            a2[k] = fmaf(y, c, a2[k]);
            if (k < 8) {
                float u = s * s;
                float p = s * c;
                c = fmaf(-2.0f, u, 1.0f);
                s = p + p;
            }
        }
    }

    // block reduction of 18 partial sums (2 warps)
    __shared__ float red[2][18];
#pragma unroll
    for (int k = 0; k < NOCT; k++) {
        a1[k] = warp_sum(a1[k]);
        a2[k] = warp_sum(a2[k]);
    }
    const int lane = threadIdx.x & 31;
    const int w    = threadIdx.x >> 5;
    if (lane == 0) {
#pragma unroll
        for (int k = 0; k < NOCT; k++) {
            red[w][k]     = a1[k];
            red[w][9 + k] = a2[k];
        }
    }
    __syncthreads();
    if (threadIdx.x < 18) {
        float v = red[0][threadIdx.x] + red[1][threadIdx.x];
        int k   = (threadIdx.x < 9) ? threadIdx.x : threadIdx.x - 9;
        int idx = b * NFREQ + k * NF0 + f0;
        if (threadIdx.x < 9) g_p1[idx] = v;
        else                 g_p2[idx] = v;
    }
}

// -------- kernel 3: magnitude + tnorm over freqs --------
__global__ __launch_bounds__(256) void finalize_kernel(float* __restrict__ out) {
    const int b = blockIdx.x;
    __shared__ float mag[NFREQ];
    __shared__ float rb[8];
    __shared__ float mean_s, inv_s;

    float acc = 0.0f;
    for (int f = threadIdx.x; f < NFREQ; f += 256) {
        float x = g_p1[b * NFREQ + f];
        float y = g_p2[b * NFREQ + f];
        float m = sqrtf(fmaf(x, x, y * y));
        mag[f] = m;
        acc += m;
    }
    acc = warp_sum(acc);
    int lane = threadIdx.x & 31, w = threadIdx.x >> 5;
    if (lane == 0) rb[w] = acc;
    __syncthreads();
    if (w == 0) {
        float v = (lane < 8) ? rb[lane] : 0.0f;
        v = warp_sum(v);
        if (lane == 0) mean_s = v * (1.0f / NFREQ);
    }
    __syncthreads();
    const float mean = mean_s;

    float acc2 = 0.0f;
    for (int f = threadIdx.x; f < NFREQ; f += 256) {
        float d = mag[f] - mean;
        acc2 = fmaf(d, d, acc2);
    }
    acc2 = warp_sum(acc2);
    __syncthreads();
    if (lane == 0) rb[w] = acc2;
    __syncthreads();
    if (w == 0) {
        float v = (lane < 8) ? rb[lane] : 0.0f;
        v = warp_sum(v);
        if (lane == 0) {
            float sd = sqrtf(v * (1.0f / (NFREQ - 1)));
            inv_s = 1.0f / (sd + 1e-4f);
        }
    }
    __syncthreads();
    const float inv = inv_s;
    for (int f = threadIdx.x; f < NFREQ; f += 256)
        out[b * NFREQ + f] = (mag[f] - mean) * inv;
}

// -------- launch --------
extern "C" void kernel_launch(void* const* d_in, const int* in_sizes, int n_in,
                              void* d_out, int out_size) {
    const float* batch = (const float*)d_in[0];   // (16, 2, 2048) f32
    const float* freqs = (const float*)d_in[1];   // (1152,) f32
    float* out = (float*)d_out;                   // (16, 1, 1152) f32

    normalize_kernel<<<BATCH, 256>>>(batch);
    spectral_kernel<<<dim3(NF0, BATCH), 64>>>(batch, freqs);
    finalize_kernel<<<BATCH, 256>>>(out);
}

// round 2
// speedup vs baseline: 1.5200x; 1.5200x over previous
#include <cuda_runtime.h>

#define T_LEN   2048
#define BATCH   16
#define NFREQ   1152
#define NOCT    9
#define NF0     128

typedef unsigned long long u64;

// -------- device scratch (no allocations allowed) --------
__device__ float g_mag[BATCH * NFREQ];
__device__ int   g_cnt[BATCH];          // zero-init; self-resetting per launch

// -------- packed f32x2 helpers --------
__device__ __forceinline__ u64 pk(float lo, float hi) {
    u64 r; asm("mov.b64 %0,{%1,%2};" : "=l"(r) : "f"(lo), "f"(hi)); return r;
}
__device__ __forceinline__ void upk(u64 v, float& lo, float& hi) {
    asm("mov.b64 {%0,%1},%2;" : "=f"(lo), "=f"(hi) : "l"(v));
}
__device__ __forceinline__ u64 fma2(u64 a, u64 b, u64 c) {
    u64 d; asm("fma.rn.f32x2 %0,%1,%2,%3;" : "=l"(d) : "l"(a), "l"(b), "l"(c)); return d;
}
__device__ __forceinline__ u64 mul2(u64 a, u64 b) {
    u64 d; asm("mul.rn.f32x2 %0,%1,%2;" : "=l"(d) : "l"(a), "l"(b)); return d;
}
__device__ __forceinline__ u64 add2(u64 a, u64 b) {
    u64 d; asm("add.rn.f32x2 %0,%1,%2;" : "=l"(d) : "l"(a), "l"(b)); return d;
}
__device__ __forceinline__ u64 sub2(u64 a, u64 b) {
    u64 d; asm("sub.rn.f32x2 %0,%1,%2;" : "=l"(d) : "l"(a), "l"(b)); return d;
}

__device__ __forceinline__ float warp_sum(float v) {
#pragma unroll
    for (int o = 16; o; o >>= 1) v += __shfl_down_sync(0xffffffffu, v, o);
    return v;
}

// -------- single fused kernel --------
// block = (f0, b); 64 threads; each thread handles 16 packed pairs of time steps.
// One packed sincos at the base octave (|arg| < 8), 8 angle doublings cover 9 octaves.
__global__ __launch_bounds__(64) void fused_kernel(const float* __restrict__ batch,
                                                   const float* __restrict__ freqs,
                                                   float* __restrict__ out) {
    const int f0  = blockIdx.x;
    const int b   = blockIdx.y;
    const int tid = threadIdx.x;
    const int lane = tid & 31, w = tid >> 5;

    const float2* __restrict__ ts2 = reinterpret_cast<const float2*>(batch + b * (2 * T_LEN));
    const float2* __restrict__ ys2 = reinterpret_cast<const float2*>(batch + b * (2 * T_LEN) + T_LEN);

    __shared__ float rb[2][2];
    __shared__ float red[2][18];
    __shared__ float fin[18];
    __shared__ int   last_s;

    // ---- prelude: per-batch mean/std of y (redundant per block, L1-resident) ----
    u64 s1 = 0, sqp = 0;
#pragma unroll
    for (int i = 0; i < 16; i++) {
        float2 y = ys2[i * 64 + tid];
        u64 yp = pk(y.x, y.y);
        s1  = add2(s1, yp);
        sqp = fma2(yp, yp, sqp);
    }
    float lo, hi;
    upk(s1, lo, hi);  float su = lo + hi;
    upk(sqp, lo, hi); float sq = lo + hi;
    su = warp_sum(su); sq = warp_sum(sq);
    if (lane == 0) { rb[w][0] = su; rb[w][1] = sq; }
    __syncthreads();
    const float Sy  = rb[0][0] + rb[1][0];
    const float Syy = rb[0][1] + rb[1][1];
    const float mean = Sy * (1.0f / T_LEN);
    const float var  = (Syy - (float)T_LEN * mean * mean) * (1.0f / (T_LEN - 1));
    const float inv  = 1.0f / (sqrtf(var) + 1e-4f);
    const float nm   = -mean * inv;

    // ---- packed constants ----
    const float w0 = freqs[f0] * 6.283185307179586f;   // base octave
    const u64 W0   = pk(w0, w0);
    const u64 INVb = pk(inv, inv);
    const u64 NMb  = pk(nm, nm);
    const u64 IPI  = pk(0.3183098861837907f, 0.3183098861837907f);
    const u64 MAG  = pk(12582912.0f, 12582912.0f);     // 2^23 + 2^22 rint magic
    const u64 PA   = pk(-3.140625f, -3.140625f);
    const u64 PB   = pk(-9.67502593994140625e-4f, -9.67502593994140625e-4f);
    const u64 PC   = pk(-1.509957990978376e-7f, -1.509957990978376e-7f);
    const u64 S11  = pk(-2.5052108385441720e-8f, -2.5052108385441720e-8f);
    const u64 S9   = pk( 2.7557319223985893e-6f,  2.7557319223985893e-6f);
    const u64 S7   = pk(-1.9841269841269841e-4f, -1.9841269841269841e-4f);
    const u64 S5   = pk( 8.3333333333333333e-3f,  8.3333333333333333e-3f);
    const u64 S3   = pk(-1.6666666666666666e-1f, -1.6666666666666666e-1f);
    const u64 C12  = pk( 2.0876756987868099e-9f,  2.0876756987868099e-9f);
    const u64 C10  = pk(-2.7557319223985893e-7f, -2.7557319223985893e-7f);
    const u64 C8   = pk( 2.4801587301587302e-5f,  2.4801587301587302e-5f);
    const u64 C6   = pk(-1.3888888888888889e-3f, -1.3888888888888889e-3f);
    const u64 C4   = pk( 4.1666666666666666e-2f,  4.1666666666666666e-2f);
    const u64 C2   = pk(-0.5f, -0.5f);
    const u64 ONE  = pk(1.0f, 1.0f);
    const u64 N2   = pk(-2.0f, -2.0f);

    u64 A1[NOCT], A2[NOCT];
#pragma unroll
    for (int k = 0; k < NOCT; k++) { A1[k] = 0; A2[k] = 0; }

    // ---- main loop: 16 packed iterations ----
#pragma unroll 4
    for (int i = 0; i < 16; i++) {
        float2 t2 = ts2[i * 64 + tid];
        float2 y2 = ys2[i * 64 + tid];
        u64 tv = pk(t2.x, t2.y);
        u64 yn = fma2(pk(y2.x, y2.y), INVb, NMb);

        // packed sincos(tv * w0): |arg| < ~8
        u64 x  = mul2(tv, W0);
        u64 qm = fma2(x, IPI, MAG);
        u64 qf = sub2(qm, MAG);
        u64 r  = fma2(qf, PA, x);
        r = fma2(qf, PB, r);
        r = fma2(qf, PC, r);
        u64 z = mul2(r, r);

        u64 ps = fma2(S11, z, S9);
        ps = fma2(ps, z, S7);
        ps = fma2(ps, z, S5);
        ps = fma2(ps, z, S3);
        u64 psz = mul2(ps, z);
        u64 s = fma2(psz, r, r);

        u64 pc = fma2(C12, z, C10);
        pc = fma2(pc, z, C8);
        pc = fma2(pc, z, C6);
        pc = fma2(pc, z, C4);
        pc = fma2(pc, z, C2);
        u64 c = fma2(pc, z, ONE);

        // parity sign from magic-biased float (bit 0) -> ALU pipe
        float qlo, qhi;
        upk(qm, qlo, qhi);
        u64 sgn = ((u64)((__float_as_uint(qhi) & 1u) << 31) << 32)
                |  (u64)((__float_as_uint(qlo) & 1u) << 31);
        s ^= sgn;
        c ^= sgn;

        // 9 octaves via angle doubling
#pragma unroll
        for (int k = 0; k < NOCT; k++) {
            A1[k] = fma2(yn, s, A1[k]);
            A2[k] = fma2(yn, c, A2[k]);
            if (k < NOCT - 1) {
                u64 u = mul2(s, s);
                u64 p = mul2(s, c);
                c = fma2(u, N2, ONE);   // cos(2t) = 1 - 2 sin^2
                s = add2(p, p);         // sin(2t) = 2 sin cos
            }
        }
    }

    // ---- block reduction of 18 sums ----
    float p1[NOCT], p2[NOCT];
#pragma unroll
    for (int k = 0; k < NOCT; k++) {
        upk(A1[k], lo, hi); p1[k] = lo + hi;
        upk(A2[k], lo, hi); p2[k] = lo + hi;
    }
#pragma unroll
    for (int k = 0; k < NOCT; k++) {
        p1[k] = warp_sum(p1[k]);
        p2[k] = warp_sum(p2[k]);
    }
    if (lane == 0) {
#pragma unroll
        for (int k = 0; k < NOCT; k++) {
            red[w][k]        = p1[k];
            red[w][NOCT + k] = p2[k];
        }
    }
    __syncthreads();
    if (tid < 18) fin[tid] = red[0][tid] + red[1][tid];
    __syncthreads();
    if (tid < NOCT) {
        float P1 = fin[tid], P2 = fin[tid + NOCT];
        g_mag[b * NFREQ + tid * NF0 + f0] = sqrtf(fmaf(P1, P1, P2 * P2));
    }
    __syncthreads();

    // ---- last-block-per-batch does the final tnorm over freqs ----
    if (tid == 0) {
        __threadfence();
        last_s = (atomicAdd(&g_cnt[b], 1) == NF0 - 1);
    }
    __syncthreads();
    if (!last_s) return;
    __threadfence();

    float mv[18];
    float sm = 0.0f, sq2 = 0.0f;
#pragma unroll
    for (int j = 0; j < 18; j++) {
        float m = __ldcg(&g_mag[b * NFREQ + j * 64 + tid]);
        mv[j] = m;
        sm += m;
        sq2 = fmaf(m, m, sq2);
    }
    sm = warp_sum(sm); sq2 = warp_sum(sq2);
    if (lane == 0) { rb[w][0] = sm; rb[w][1] = sq2; }
    __syncthreads();
    const float Sm = rb[0][0] + rb[1][0];
    const float Sq = rb[0][1] + rb[1][1];
    const float mmean = Sm * (1.0f / NFREQ);
    const float mvar  = (Sq - (float)NFREQ * mmean * mmean) * (1.0f / (NFREQ - 1));
    const float minv  = 1.0f / (sqrtf(mvar) + 1e-4f);
#pragma unroll
    for (int j = 0; j < 18; j++)
        out[b * NFREQ + j * 64 + tid] = (mv[j] - mmean) * minv;

    if (tid == 0) g_cnt[b] = 0;   // reset for next graph replay
}

// -------- launch --------
extern "C" void kernel_launch(void* const* d_in, const int* in_sizes, int n_in,
                              void* d_out, int out_size) {
    const float* batch = (const float*)d_in[0];   // (16, 2, 2048) f32
    const float* freqs = (const float*)d_in[1];   // (1152,) f32
    float* out = (float*)d_out;                   // (16, 1, 1152) f32

    fused_kernel<<<dim3(NF0, BATCH), 64>>>(batch, freqs, out);
}